// round 11
// baseline (speedup 1.0000x reference)
#include <cuda_runtime.h>

using u64 = unsigned long long;

// ---------------- problem constants -----------------------------------------
constexpr int Bn = 4;
constexpr int Nn = 8192;
constexpr int M2 = 8192;
constexpr int M3 = 4096;
constexpr int M4 = 2048;
constexpr int MM = 4096;

constexpr int NB = 128;                 // 1D x bins
constexpr float XMIN = -64.f;
constexpr float WBIN = 1.0f;
constexpr float BIG  = 3.0e38f;
constexpr float MARG = 0.0625f;         // expansion margin >> fp error of d
constexpr unsigned FULL = 0xFFFFFFFFu;
constexpr int TOTAL_ELEMS = Bn * (M2 + M3 + M4 + MM + Nn);   // 106496

// padded group capacities per batch (elements padded to x4 per bin)
constexpr int CAPG2 = (M2 + 3 * NB) / 4;    // 2144 groups
constexpr int CAPG3 = (M3 + 3 * NB) / 4;    // 1120
constexpr int CAPG4 = (M4 + 3 * NB) / 4;    // 608
constexpr int CAPGM = (MM + 3 * NB) / 4;    // 1120

// ---------------- device scratch ---------------------------------------------
// interp record per 4-cand group: [x4|y4|z4|kk4|fv4] = 80 B; mask: 64 B
__device__ __align__(16) float g2buf[Bn * CAPG2 * 20];
__device__ __align__(16) float g3buf[Bn * CAPG3 * 20];
__device__ __align__(16) float g4buf[Bn * CAPG4 * 20];
__device__ __align__(16) float gmbuf[Bn * CAPGM * 16];
__device__ float qsx[Bn * Nn], qsy[Bn * Nn], qsz[Bn * Nn];
__device__ int   qsi[Bn * Nn];
__device__ int   gcnt[20 * NB];          // arr = set(0..2)*4+b | 12+b | 16+b
__device__ int   gfil[20 * NB];
__device__ int   goffs[20 * (NB + 1)];
__device__ float g_v[96];

// ---------------- packed f32x2 helpers ----------------------------------------
__device__ __forceinline__ u64 ffma2u(u64 a, u64 b, u64 c) {
    u64 r;
    asm("fma.rn.f32x2 %0, %1, %2, %3;" : "=l"(r) : "l"(a), "l"(b), "l"(c));
    return r;
}
__device__ __forceinline__ u64 fadd2u(u64 a, u64 b) {
    u64 r;
    asm("add.rn.f32x2 %0, %1, %2;" : "=l"(r) : "l"(a), "l"(b));
    return r;
}
__device__ __forceinline__ float lo_(u64 v) { return __uint_as_float((unsigned)v); }
__device__ __forceinline__ float hi_(u64 v) { return __uint_as_float((unsigned)(v >> 32)); }
__device__ __forceinline__ u64 dup2(float x) {
    unsigned b = __float_as_uint(x);
    return ((u64)b << 32) | (u64)b;
}
__device__ __forceinline__ int bin_of(float v) {
    int c = (int)(v - XMIN);
    return min(max(c, 0), NB - 1);
}

// ---------------- element decode ------------------------------------------------
__device__ __forceinline__ void decode(int idx, int& arr, int& il, int& flat) {
    if (idx < 32768)      { arr = (idx >> 13);           il = idx & 8191; flat = idx; }
    else if (idx < 49152) { int j = idx - 32768; arr = 4  + (j >> 12); il = j & 4095; flat = j; }
    else if (idx < 57344) { int j = idx - 49152; arr = 8  + (j >> 11); il = j & 2047; flat = j; }
    else if (idx < 73728) { int j = idx - 57344; arr = 12 + (j >> 12); il = j & 4095; flat = j; }
    else                  { int j = idx - 73728; arr = 16 + (j >> 13); il = j & 8191; flat = j; }
}
__device__ __forceinline__ const float* src_of(int arr,
    const float* k2, const float* k3, const float* k4,
    const float* mp, const float* pt)
{
    if (arr < 4)  return k2;
    if (arr < 8)  return k3;
    if (arr < 12) return k4;
    if (arr < 16) return mp;
    return pt;
}

// ---------------- K0: sentinel-init record buffers + zero counters ---------------
__global__ void init_kernel() {
    int i = blockIdx.x * 256 + threadIdx.x;
    constexpr int A = Bn * CAPG2;                 // 8576
    constexpr int B = A + Bn * CAPG3;             // 13056
    constexpr int C = B + Bn * CAPG4;             // 15488
    constexpr int D = C + Bn * CAPGM;             // 19968
    constexpr int E = D + 20 * NB;                // 22528
    const float4 z4 = make_float4(0.f, 0.f, 0.f, 0.f);
    const float4 s4 = make_float4(1e30f, 1e30f, 1e30f, 1e30f);
    if (i < C) {
        float* gp;
        if (i < A)      gp = g2buf + (size_t)i * 20;
        else if (i < B) gp = g3buf + (size_t)(i - A) * 20;
        else            gp = g4buf + (size_t)(i - B) * 20;
        float4* p = reinterpret_cast<float4*>(gp);
        p[0] = z4; p[1] = z4; p[2] = z4; p[3] = s4; p[4] = z4;
    } else if (i < D) {
        float4* p = reinterpret_cast<float4*>(gmbuf + (size_t)(i - C) * 16);
        p[0] = z4; p[1] = z4; p[2] = z4; p[3] = s4;
    } else if (i < E) {
        gcnt[i - D] = 0; gfil[i - D] = 0;
    }
}

// ---------------- K1: histogram + g_v ---------------------------------------------
__global__ void hist_kernel(const float* __restrict__ k2, const float* __restrict__ k3,
    const float* __restrict__ k4, const float* __restrict__ mp,
    const float* __restrict__ pt,
    const float* __restrict__ w_fc, const float* __restrict__ w_cls)
{
    int idx = blockIdx.x * 256 + threadIdx.x;
    if (blockIdx.x == 0 && threadIdx.x < 96) {
        float acc = 0.f;
#pragma unroll
        for (int k = 0; k < 64; k++)
            acc = fmaf(w_cls[k], w_fc[k * 96 + threadIdx.x], acc);
        g_v[threadIdx.x] = acc;
    }
    if (idx >= TOTAL_ELEMS) return;
    int arr, il, flat;
    decode(idx, arr, il, flat);
    const float* src = src_of(arr, k2, k3, k4, mp, pt);
    atomicAdd(&gcnt[arr * NB + bin_of(src[flat * 3])], 1);
}

// ---------------- K2: per-array exclusive prefix (padded counts) -------------------
__global__ void prefix_kernel() {
    int w = threadIdx.x >> 5, lane = threadIdx.x & 31;
    if (w >= 20) return;
    bool pad = (w < 16);
    int run = 0;
    for (int c0 = 0; c0 < NB; c0 += 32) {
        int bb = c0 + lane;
        int c = gcnt[w * NB + bb];
        if (pad) c = (c + 3) & ~3;
        int v = c;
#pragma unroll
        for (int o = 1; o < 32; o <<= 1) {
            int u = __shfl_up_sync(FULL, v, o);
            if (lane >= o) v += u;
        }
        goffs[w * (NB + 1) + bb] = run + v - c;
        run += __shfl_sync(FULL, v, 31);
    }
    if (lane == 0) goffs[w * (NB + 1) + NB] = run;
}

// ---------------- K3: scatter into padded binned records ---------------------------
__global__ void scatter_kernel(const float* __restrict__ k2, const float* __restrict__ f2,
    const float* __restrict__ k3, const float* __restrict__ f3,
    const float* __restrict__ k4, const float* __restrict__ f4,
    const float* __restrict__ mp, const float* __restrict__ pt)
{
    int idx = blockIdx.x * 256 + threadIdx.x;
    if (idx >= TOTAL_ELEMS) return;
    int arr, il, flat;
    decode(idx, arr, il, flat);
    const float* src = src_of(arr, k2, k3, k4, mp, pt);
    float x = src[flat * 3 + 0];
    float y = src[flat * 3 + 1];
    float z = src[flat * 3 + 2];
    // same rounding order as jnp.sum(p*p, -1)
    float kk = __fadd_rn(__fadd_rn(__fmul_rn(x, x), __fmul_rn(y, y)), __fmul_rn(z, z));
    int bb = bin_of(x);
    int pos = goffs[arr * (NB + 1) + bb] + atomicAdd(&gfil[arr * NB + bb], 1);
    int b = arr & 3;

    if (arr < 12) {
        const float* feats; int voff; float* buf; int capg;
        if (arr < 4)      { feats = f2; voff = 0;  buf = g2buf; capg = CAPG2; }
        else if (arr < 8) { feats = f3; voff = 32; buf = g3buf; capg = CAPG3; }
        else              { feats = f4; voff = 64; buf = g4buf; capg = CAPG4; }
        float acc = 0.f;
        const float4* fp = reinterpret_cast<const float4*>(feats + (size_t)flat * 32);
#pragma unroll
        for (int j = 0; j < 8; j++) {
            float4 t = fp[j];
            acc = fmaf(t.x, g_v[voff + 4 * j + 0], acc);
            acc = fmaf(t.y, g_v[voff + 4 * j + 1], acc);
            acc = fmaf(t.z, g_v[voff + 4 * j + 2], acc);
            acc = fmaf(t.w, g_v[voff + 4 * j + 3], acc);
        }
        float* gp = buf + (size_t)(b * capg + (pos >> 2)) * 20;
        int sl = pos & 3;
        gp[sl] = x; gp[4 + sl] = y; gp[8 + sl] = z; gp[12 + sl] = kk; gp[16 + sl] = acc;
    } else if (arr < 16) {
        float* gp = gmbuf + (size_t)(b * CAPGM + (pos >> 2)) * 16;
        int sl = pos & 3;
        gp[sl] = x; gp[4 + sl] = y; gp[8 + sl] = z; gp[12 + sl] = kk;
    } else {
        int o = b * Nn + pos;
        qsx[o] = x; qsy[o] = y; qsz[o] = z;
        qsi[o] = b * Nn + il;                   // original global query index
    }
}

// ---------------- top-3 maintenance --------------------------------------------------
__device__ __forceinline__ void try_ins(float e, float fv,
                                        float& t0, float& t1, float& t2,
                                        float& f0, float& f1, float& f2) {
    if (e < t2) {
        if (e < t1) {
            t2 = t1; f2 = f1;
            if (e < t0) { t1 = t0; f1 = f0; t0 = e; f0 = fv; }
            else        { t1 = e;  f1 = fv; }
        } else { t2 = e; f2 = fv; }
    }
}

// one 4-cand group vs this lane's query; record address is warp-uniform
__device__ __forceinline__ void scan_group_i(const float* buf, int g,
    u64 c2x, u64 c2y, u64 c2z, u64 qq2,
    float& t0, float& t1, float& t2, float& f0, float& f1, float& f2)
{
    const char* p = reinterpret_cast<const char*>(buf) + (size_t)g * 80;
    ulonglong2 X = __ldg(reinterpret_cast<const ulonglong2*>(p));
    ulonglong2 Y = __ldg(reinterpret_cast<const ulonglong2*>(p + 16));
    ulonglong2 Z = __ldg(reinterpret_cast<const ulonglong2*>(p + 32));
    ulonglong2 W = __ldg(reinterpret_cast<const ulonglong2*>(p + 48));
    float4     F = __ldg(reinterpret_cast<const float4*>(p + 64));
    // d = (qq+kk) - 2*dot, reference rounding order
    u64 dl = fadd2u(qq2, W.x);
    dl = ffma2u(c2x, X.x, dl); dl = ffma2u(c2y, Y.x, dl); dl = ffma2u(c2z, Z.x, dl);
    u64 dh = fadd2u(qq2, W.y);
    dh = ffma2u(c2x, X.y, dh); dh = ffma2u(c2y, Y.y, dh); dh = ffma2u(c2z, Z.y, dh);
    float d0 = lo_(dl), d1 = hi_(dl), d2 = lo_(dh), d3 = hi_(dh);
    float m = fminf(fminf(d0, d1), fminf(d2, d3));
    if (m < t2) {
        try_ins(d0, F.x, t0, t1, t2, f0, f1, f2);
        try_ins(d1, F.y, t0, t1, t2, f0, f1, f2);
        try_ins(d2, F.z, t0, t1, t2, f0, f1, f2);
        try_ins(d3, F.w, t0, t1, t2, f0, f1, f2);
    }
}

// ---------------- K4: scan — 32 x-sorted queries per warp, one per lane -------------
__global__ void __launch_bounds__(128)
scan_kernel(float* __restrict__ out) {
    const int warp = (blockIdx.x * 128 + threadIdx.x) >> 5;
    const int lane = threadIdx.x & 31;
    const int b    = warp >> 8;                  // 256 warps per batch
    const int qo   = b * Nn + (warp & 255) * 32 + lane;

    const float x = qsx[qo], y = qsy[qo], z = qsz[qo];
    const int   oi = qsi[qo];
    const float qq = __fadd_rn(__fadd_rn(__fmul_rn(x, x), __fmul_rn(y, y)),
                               __fmul_rn(z, z));
    const u64 c2x = dup2(-2.f * x), c2y = dup2(-2.f * y), c2z = dup2(-2.f * z);
    const u64 qq2 = dup2(qq);

    // warp-shared x-bin window
    int cb = bin_of(x);
    int cmin = cb, cmax = cb;
#pragma unroll
    for (int o = 16; o; o >>= 1) {
        cmin = min(cmin, __shfl_xor_sync(FULL, cmin, o));
        cmax = max(cmax, __shfl_xor_sync(FULL, cmax, o));
    }

    float pred = 0.f;
    const float* bufs[3] = { g2buf, g3buf, g4buf };
    const int    caps[3] = { CAPG2, CAPG3, CAPG4 };

#pragma unroll 1
    for (int s = 0; s < 3; s++) {
        const float* buf = bufs[s];
        const int* offs = goffs + (s * 4 + b) * (NB + 1);
        const int gb0 = b * caps[s];
        float t0 = BIG, t1 = BIG, t2 = BIG, f0 = 0.f, f1 = 0.f, f2 = 0.f;

        int bl = max(cmin - 1, 0), bh = min(cmax + 1, NB - 1);
        {
            int gs = gb0 + (__ldg(offs + bl) >> 2);
            int ge = gb0 + (__ldg(offs + bh + 1) >> 2);
#pragma unroll 2
            for (int g = gs; g < ge; g++)
                scan_group_i(buf, g, c2x, c2y, c2z, qq2, t0, t1, t2, f0, f1, f2);
        }
        while (true) {
            float eL = XMIN + bl * WBIN;        // unscanned left cands: x <= eL
            float eR = XMIN + (bh + 1) * WBIN;  // unscanned right cands: x >= eR
            float dL = x - eL, dR = eR - x;
            bool nL = (bl > 0)      && (dL * dL < t2 + MARG);
            bool nR = (bh < NB - 1) && (dR * dR < t2 + MARG);
            unsigned mL = __ballot_sync(FULL, nL);
            unsigned mR = __ballot_sync(FULL, nR);
            if (!mL && !mR) break;
            if (mL) {
                bl--;
                int gs = gb0 + (__ldg(offs + bl) >> 2);
                int ge = gb0 + (__ldg(offs + bl + 1) >> 2);
                for (int g = gs; g < ge; g++)
                    scan_group_i(buf, g, c2x, c2y, c2z, qq2, t0, t1, t2, f0, f1, f2);
            }
            if (mR) {
                bh++;
                int gs = gb0 + (__ldg(offs + bh) >> 2);
                int ge = gb0 + (__ldg(offs + bh + 1) >> 2);
                for (int g = gs; g < ge; g++)
                    scan_group_i(buf, g, c2x, c2y, c2z, qq2, t0, t1, t2, f0, f1, f2);
            }
        }
        float d0 = fmaxf(t0, 0.f), d1 = fmaxf(t1, 0.f), d2c = fmaxf(t2, 0.f);
        float r0 = 1.f / (d0 + 1e-8f);
        float r1 = 1.f / (d1 + 1e-8f);
        float r2 = 1.f / (d2c + 1e-8f);
        pred += fmaf(r0, f0, fmaf(r1, f1, r2 * f2)) / (r0 + r1 + r2);
    }

    // ---- mask: any(d2 < 0.25) over bins [cmin-1, cmax+1] (>=1m gap > 0.5m) ----
    int found = 0;
    {
        const int* offs = goffs + (12 + b) * (NB + 1);
        const int gb0 = b * CAPGM;
        int bl = max(cmin - 1, 0), bh = min(cmax + 1, NB - 1);
        int gs = gb0 + (__ldg(offs + bl) >> 2);
        int ge = gb0 + (__ldg(offs + bh + 1) >> 2);
        float tf = 0.3125f - qq;                 // margin fast path
#pragma unroll 2
        for (int g = gs; g < ge; g++) {
            const char* p = reinterpret_cast<const char*>(gmbuf) + (size_t)g * 64;
            ulonglong2 X = __ldg(reinterpret_cast<const ulonglong2*>(p));
            ulonglong2 Y = __ldg(reinterpret_cast<const ulonglong2*>(p + 16));
            ulonglong2 Z = __ldg(reinterpret_cast<const ulonglong2*>(p + 32));
            ulonglong2 W = __ldg(reinterpret_cast<const ulonglong2*>(p + 48));
            // fast path: e = kk - 2*dot (qq deferred; protected by margin)
            u64 el = ffma2u(c2x, X.x, ffma2u(c2y, Y.x, ffma2u(c2z, Z.x, W.x)));
            u64 eh = ffma2u(c2x, X.y, ffma2u(c2y, Y.y, ffma2u(c2z, Z.y, W.y)));
            float m = fminf(fminf(lo_(el), hi_(el)), fminf(lo_(eh), hi_(eh)));
            if (m < tf) {                        // rare: exact recheck
                float cx[4] = { lo_(X.x), hi_(X.x), lo_(X.y), hi_(X.y) };
                float cy[4] = { lo_(Y.x), hi_(Y.x), lo_(Y.y), hi_(Y.y) };
                float cz[4] = { lo_(Z.x), hi_(Z.x), lo_(Z.y), hi_(Z.y) };
                float cw[4] = { lo_(W.x), hi_(W.x), lo_(W.y), hi_(W.y) };
#pragma unroll
                for (int c = 0; c < 4; c++) {
                    // bit-exact reference-mimic rounding
                    float dot = __fadd_rn(__fadd_rn(__fmul_rn(x, cx[c]),
                                                    __fmul_rn(y, cy[c])),
                                          __fmul_rn(z, cz[c]));
                    float d = __fsub_rn(__fadd_rn(qq, cw[c]), __fadd_rn(dot, dot));
                    if (d < 0.25f) found = 1;
                }
            }
        }
    }

    out[oi] = pred;                              // pred_hm (B,N,1)
    out[Bn * Nn + oi] = found ? 1.f : 0.f;       // gt_hm   (B,N)
}

// ---------------- launch ---------------------------------------------------------------
extern "C" void kernel_launch(void* const* d_in, const int* in_sizes, int n_in,
                              void* d_out, int out_size) {
    (void)in_sizes; (void)n_in; (void)out_size;
    const float* pts    = (const float*)d_in[0];
    const float* known2 = (const float*)d_in[1];
    const float* feats2 = (const float*)d_in[2];
    const float* known3 = (const float*)d_in[3];
    const float* feats3 = (const float*)d_in[4];
    const float* known4 = (const float*)d_in[5];
    const float* feats4 = (const float*)d_in[6];
    const float* matchp = (const float*)d_in[7];
    const float* w_fc   = (const float*)d_in[8];
    const float* w_cls  = (const float*)d_in[9];
    float* out = (float*)d_out;

    constexpr int INIT_N = Bn * (CAPG2 + CAPG3 + CAPG4 + CAPGM) + 20 * NB;
    const int eb = (TOTAL_ELEMS + 255) / 256;
    init_kernel<<<(INIT_N + 255) / 256, 256>>>();
    hist_kernel<<<eb, 256>>>(known2, known3, known4, matchp, pts, w_fc, w_cls);
    prefix_kernel<<<1, 640>>>();
    scatter_kernel<<<eb, 256>>>(known2, feats2, known3, feats3,
                                known4, feats4, matchp, pts);
    scan_kernel<<<(Bn * Nn) / 128 / 32 * 32, 128>>>(out);   // 1024 warps, 128/blk
}

// round 12
// speedup vs baseline: 1.6977x; 1.6977x over previous
#include <cuda_runtime.h>

using u64 = unsigned long long;

// ---------------- problem constants -----------------------------------------
constexpr int Bn = 4;
constexpr int Nn = 8192;
constexpr int M2 = 8192;
constexpr int M3 = 4096;
constexpr int M4 = 2048;
constexpr int MM = 4096;

constexpr int NB = 128;                 // 1D x bins, 1m wide
constexpr float XMIN = -64.f;
constexpr float WBIN = 1.0f;
constexpr float BIG  = 3.0e38f;
constexpr float SENT = 1e29f;           // "no group" marker threshold
constexpr float MARG = 0.0625f;         // expansion margin >> fp error of d
constexpr unsigned FULL = 0xFFFFFFFFu;
constexpr int TOTAL_ELEMS = Bn * (M2 + M3 + M4 + MM + Nn);   // 106496

// padded group capacities per batch (elements padded to x4 per bin)
constexpr int CAPG2 = (M2 + 3 * NB) / 4;    // 2144 groups
constexpr int CAPG3 = (M3 + 3 * NB) / 4;    // 1120
constexpr int CAPG4 = (M4 + 3 * NB) / 4;    // 608
constexpr int CAPGM = (MM + 3 * NB) / 4;    // 1120

// ---------------- device scratch ---------------------------------------------
// all records are 16 floats per 4-cand group: [x4|y4|z4|kk4] = 64 B
__device__ __align__(16) float g2buf[Bn * CAPG2 * 16];
__device__ __align__(16) float g3buf[Bn * CAPG3 * 16];
__device__ __align__(16) float g4buf[Bn * CAPG4 * 16];
__device__ __align__(16) float gmbuf[Bn * CAPGM * 16];
// fv payloads, float4 per group, only touched in the rescan post-pass
__device__ __align__(16) float fv2buf[Bn * CAPG2 * 4];
__device__ __align__(16) float fv3buf[Bn * CAPG3 * 4];
__device__ __align__(16) float fv4buf[Bn * CAPG4 * 4];
__device__ float qsx[Bn * Nn], qsy[Bn * Nn], qsz[Bn * Nn];
__device__ int   qsi[Bn * Nn];
__device__ int   gcnt[20 * NB];          // arr = set(0..2)*4+b | 12+b | 16+b
__device__ int   gfil[20 * NB];
__device__ int   goffs[20 * (NB + 1)];
__device__ float g_v[96];

// ---------------- packed f32x2 helpers ----------------------------------------
__device__ __forceinline__ u64 ffma2u(u64 a, u64 b, u64 c) {
    u64 r;
    asm("fma.rn.f32x2 %0, %1, %2, %3;" : "=l"(r) : "l"(a), "l"(b), "l"(c));
    return r;
}
__device__ __forceinline__ u64 fadd2u(u64 a, u64 b) {
    u64 r;
    asm("add.rn.f32x2 %0, %1, %2;" : "=l"(r) : "l"(a), "l"(b));
    return r;
}
__device__ __forceinline__ float lo_(u64 v) { return __uint_as_float((unsigned)v); }
__device__ __forceinline__ float hi_(u64 v) { return __uint_as_float((unsigned)(v >> 32)); }
__device__ __forceinline__ u64 dup2(float x) {
    unsigned b = __float_as_uint(x);
    return ((u64)b << 32) | (u64)b;
}
__device__ __forceinline__ int bin_of(float v) {
    int c = (int)(v - XMIN);
    return min(max(c, 0), NB - 1);
}

// ---------------- element decode ------------------------------------------------
__device__ __forceinline__ void decode(int idx, int& arr, int& il, int& flat) {
    if (idx < 32768)      { arr = (idx >> 13);           il = idx & 8191; flat = idx; }
    else if (idx < 49152) { int j = idx - 32768; arr = 4  + (j >> 12); il = j & 4095; flat = j; }
    else if (idx < 57344) { int j = idx - 49152; arr = 8  + (j >> 11); il = j & 2047; flat = j; }
    else if (idx < 73728) { int j = idx - 57344; arr = 12 + (j >> 12); il = j & 4095; flat = j; }
    else                  { int j = idx - 73728; arr = 16 + (j >> 13); il = j & 8191; flat = j; }
}
__device__ __forceinline__ const float* src_of(int arr,
    const float* k2, const float* k3, const float* k4,
    const float* mp, const float* pt)
{
    if (arr < 4)  return k2;
    if (arr < 8)  return k3;
    if (arr < 12) return k4;
    if (arr < 16) return mp;
    return pt;
}

// ---------------- K0: sentinel-init record buffers + zero counters ---------------
__global__ void init_kernel() {
    int i = blockIdx.x * 256 + threadIdx.x;
    constexpr int A = Bn * CAPG2;                 // 8576
    constexpr int B = A + Bn * CAPG3;             // 13056
    constexpr int C = B + Bn * CAPG4;             // 15488
    constexpr int D = C + Bn * CAPGM;             // 19968
    constexpr int E = D + 20 * NB;                // 22528
    const float4 z4 = make_float4(0.f, 0.f, 0.f, 0.f);
    const float4 s4 = make_float4(1e30f, 1e30f, 1e30f, 1e30f);
    if (i < D) {
        float* gp;
        if (i < A)      gp = g2buf + (size_t)i * 16;
        else if (i < B) gp = g3buf + (size_t)(i - A) * 16;
        else if (i < C) gp = g4buf + (size_t)(i - B) * 16;
        else            gp = gmbuf + (size_t)(i - C) * 16;
        float4* p = reinterpret_cast<float4*>(gp);
        p[0] = z4; p[1] = z4; p[2] = z4; p[3] = s4;     // kk=1e30 sentinels
    } else if (i < E) {
        gcnt[i - D] = 0; gfil[i - D] = 0;
    }
}

// ---------------- K1: histogram + g_v ---------------------------------------------
__global__ void hist_kernel(const float* __restrict__ k2, const float* __restrict__ k3,
    const float* __restrict__ k4, const float* __restrict__ mp,
    const float* __restrict__ pt,
    const float* __restrict__ w_fc, const float* __restrict__ w_cls)
{
    int idx = blockIdx.x * 256 + threadIdx.x;
    if (blockIdx.x == 0 && threadIdx.x < 96) {
        float acc = 0.f;
#pragma unroll
        for (int k = 0; k < 64; k++)
            acc = fmaf(w_cls[k], w_fc[k * 96 + threadIdx.x], acc);
        g_v[threadIdx.x] = acc;
    }
    if (idx >= TOTAL_ELEMS) return;
    int arr, il, flat;
    decode(idx, arr, il, flat);
    const float* src = src_of(arr, k2, k3, k4, mp, pt);
    atomicAdd(&gcnt[arr * NB + bin_of(src[flat * 3])], 1);
}

// ---------------- K2: per-array exclusive prefix (padded counts) -------------------
__global__ void prefix_kernel() {
    int w = threadIdx.x >> 5, lane = threadIdx.x & 31;
    if (w >= 20) return;
    bool pad = (w < 16);
    int run = 0;
    for (int c0 = 0; c0 < NB; c0 += 32) {
        int bb = c0 + lane;
        int c = gcnt[w * NB + bb];
        if (pad) c = (c + 3) & ~3;
        int v = c;
#pragma unroll
        for (int o = 1; o < 32; o <<= 1) {
            int u = __shfl_up_sync(FULL, v, o);
            if (lane >= o) v += u;
        }
        goffs[w * (NB + 1) + bb] = run + v - c;
        run += __shfl_sync(FULL, v, 31);
    }
    if (lane == 0) goffs[w * (NB + 1) + NB] = run;
}

// ---------------- K3: scatter into padded binned records ---------------------------
__global__ void scatter_kernel(const float* __restrict__ k2, const float* __restrict__ f2,
    const float* __restrict__ k3, const float* __restrict__ f3,
    const float* __restrict__ k4, const float* __restrict__ f4,
    const float* __restrict__ mp, const float* __restrict__ pt)
{
    int idx = blockIdx.x * 256 + threadIdx.x;
    if (idx >= TOTAL_ELEMS) return;
    int arr, il, flat;
    decode(idx, arr, il, flat);
    const float* src = src_of(arr, k2, k3, k4, mp, pt);
    float x = src[flat * 3 + 0];
    float y = src[flat * 3 + 1];
    float z = src[flat * 3 + 2];
    // same rounding order as jnp.sum(p*p, -1)
    float kk = __fadd_rn(__fadd_rn(__fmul_rn(x, x), __fmul_rn(y, y)), __fmul_rn(z, z));
    int bb = bin_of(x);
    int pos = goffs[arr * (NB + 1) + bb] + atomicAdd(&gfil[arr * NB + bb], 1);
    int b = arr & 3;

    if (arr < 12) {
        const float* feats; int voff; float* buf; float* fvb; int capg;
        if (arr < 4)      { feats = f2; voff = 0;  buf = g2buf; fvb = fv2buf; capg = CAPG2; }
        else if (arr < 8) { feats = f3; voff = 32; buf = g3buf; fvb = fv3buf; capg = CAPG3; }
        else              { feats = f4; voff = 64; buf = g4buf; fvb = fv4buf; capg = CAPG4; }
        float acc = 0.f;
        const float4* fp = reinterpret_cast<const float4*>(feats + (size_t)flat * 32);
#pragma unroll
        for (int j = 0; j < 8; j++) {
            float4 t = fp[j];
            acc = fmaf(t.x, g_v[voff + 4 * j + 0], acc);
            acc = fmaf(t.y, g_v[voff + 4 * j + 1], acc);
            acc = fmaf(t.z, g_v[voff + 4 * j + 2], acc);
            acc = fmaf(t.w, g_v[voff + 4 * j + 3], acc);
        }
        int grp = b * capg + (pos >> 2);
        float* gp = buf + (size_t)grp * 16;
        int sl = pos & 3;
        gp[sl] = x; gp[4 + sl] = y; gp[8 + sl] = z; gp[12 + sl] = kk;
        fvb[grp * 4 + sl] = acc;
    } else if (arr < 16) {
        float* gp = gmbuf + (size_t)(b * CAPGM + (pos >> 2)) * 16;
        int sl = pos & 3;
        gp[sl] = x; gp[4 + sl] = y; gp[8 + sl] = z; gp[12 + sl] = kk;
    } else {
        int o = b * Nn + pos;
        qsx[o] = x; qsy[o] = y; qsz[o] = z;
        qsi[o] = b * Nn + il;                   // original global query index
    }
}

// ---------------- top-3 maintenance --------------------------------------------------
__device__ __forceinline__ void try_ins(float e, float fv,
                                        float& t0, float& t1, float& t2,
                                        float& f0, float& f1, float& f2) {
    if (e < t2) {
        if (e < t1) {
            t2 = t1; f2 = f1;
            if (e < t0) { t1 = t0; f1 = f0; t0 = e; f0 = fv; }
            else        { t1 = e;  f1 = fv; }
        } else { t2 = e; f2 = fv; }
    }
}
__device__ __forceinline__ void try_ins_g(float e, int g,
                                          float& m0, float& m1, float& m2,
                                          int& g0, int& g1, int& g2) {
    if (e < m2) {
        if (e < m1) {
            m2 = m1; g2 = g1;
            if (e < m0) { m1 = m0; g1 = g0; m0 = e; g0 = g; }
            else        { m1 = e;  g1 = g; }
        } else { m2 = e; g2 = g; }
    }
}

// packed distances for one 64B group record (reference rounding order)
__device__ __forceinline__ void group_d(const float* buf, int g,
    u64 c2x, u64 c2y, u64 c2z, u64 qq2,
    float& d0, float& d1, float& d2, float& d3)
{
    const char* p = reinterpret_cast<const char*>(buf) + (size_t)g * 64;
    ulonglong2 X = __ldg(reinterpret_cast<const ulonglong2*>(p));
    ulonglong2 Y = __ldg(reinterpret_cast<const ulonglong2*>(p + 16));
    ulonglong2 Z = __ldg(reinterpret_cast<const ulonglong2*>(p + 32));
    ulonglong2 W = __ldg(reinterpret_cast<const ulonglong2*>(p + 48));
    u64 dl = fadd2u(qq2, W.x);
    dl = ffma2u(c2x, X.x, dl); dl = ffma2u(c2y, Y.x, dl); dl = ffma2u(c2z, Z.x, dl);
    u64 dh = fadd2u(qq2, W.y);
    dh = ffma2u(c2x, X.y, dh); dh = ffma2u(c2y, Y.y, dh); dh = ffma2u(c2z, Z.y, dh);
    d0 = lo_(dl); d1 = hi_(dl); d2 = lo_(dh); d3 = hi_(dh);
}

// hot loop: only (group-min, group-id) top-3, single gated insert
__device__ __forceinline__ void scan_group_min(const float* buf, int g,
    u64 c2x, u64 c2y, u64 c2z, u64 qq2,
    float& m0, float& m1, float& m2, int& g0, int& g1, int& g2)
{
    float d0, d1, d2, d3;
    group_d(buf, g, c2x, c2y, c2z, qq2, d0, d1, d2, d3);
    float m = fminf(fminf(d0, d1), fminf(d2, d3));
    if (m < m2) try_ins_g(m, g, m0, m1, m2, g0, g1, g2);
}

// ---------------- K4: scan (4-lane teams, 8 queries/warp) ----------------------------
__global__ void __launch_bounds__(256)
scan_kernel(float* __restrict__ out) {
    const int W    = blockIdx.x * 8 + (threadIdx.x >> 5);
    const int lane = threadIdx.x & 31;
    const int sub  = lane & 3;
    const int b    = W >> 10;
    const int qo   = b * Nn + (W & 1023) * 8 + (lane >> 2);

    const float x = qsx[qo], y = qsy[qo], z = qsz[qo];
    const int   oi = qsi[qo];
    const float qq = __fadd_rn(__fadd_rn(__fmul_rn(x, x), __fmul_rn(y, y)),
                               __fmul_rn(z, z));
    const u64 c2x = dup2(-2.f * x), c2y = dup2(-2.f * y), c2z = dup2(-2.f * z);
    const u64 qq2 = dup2(qq);

    // warp-shared x-bin window
    int cb = bin_of(x);
    int cmin = cb, cmax = cb;
#pragma unroll
    for (int o = 16; o; o >>= 1) {
        cmin = min(cmin, __shfl_xor_sync(FULL, cmin, o));
        cmax = max(cmax, __shfl_xor_sync(FULL, cmax, o));
    }

    float pred = 0.f;
    const float* bufs[3]   = { g2buf, g3buf, g4buf };
    const float* fvbufs[3] = { fv2buf, fv3buf, fv4buf };
    const int    caps[3]   = { CAPG2, CAPG3, CAPG4 };

#pragma unroll 1
    for (int s = 0; s < 3; s++) {
        const float* buf = bufs[s];
        const int* offs = goffs + (s * 4 + b) * (NB + 1);
        const int gb0 = b * caps[s];

        float m0 = BIG, m1 = BIG, m2 = BIG;
        int   g0 = -1,  g1 = -1,  g2 = -1;

        int bl = max(cmin - 1, 0), bh = min(cmax + 1, NB - 1);
        int gslo = gb0 + (__ldg(offs + bl) >> 2);
        int gshi = gb0 + (__ldg(offs + bh + 1) >> 2);
#pragma unroll 2
        for (int g = gslo + sub; g < gshi; g += 4)
            scan_group_min(buf, g, c2x, c2y, c2z, qq2, m0, m1, m2, g0, g1, g2);

        while (true) {
            float eL = XMIN + bl * WBIN;        // unscanned left cands: x <= eL
            float eR = XMIN + (bh + 1) * WBIN;  // unscanned right cands: x >= eR
            float dL = x - eL, dR = eR - x;
            // m2 >= true t2 -> conservative expansion bound
            bool nL = (bl > 0)      && (dL * dL < m2 + MARG);
            bool nR = (bh < NB - 1) && (dR * dR < m2 + MARG);
            unsigned mL = __ballot_sync(FULL, nL);
            unsigned mR = __ballot_sync(FULL, nR);
            if (!mL && !mR) break;
            if (mL) {
                bl--;
                int nlo = gb0 + (__ldg(offs + bl) >> 2);
                for (int g = nlo + sub; g < gslo; g += 4)
                    scan_group_min(buf, g, c2x, c2y, c2z, qq2, m0, m1, m2, g0, g1, g2);
                gslo = nlo;
            }
            if (mR) {
                bh++;
                int nhi = gb0 + (__ldg(offs + bh + 1) >> 2);
                for (int g = gshi + sub; g < nhi; g += 4)
                    scan_group_min(buf, g, c2x, c2y, c2z, qq2, m0, m1, m2, g0, g1, g2);
                gshi = nhi;
            }
        }

        // rescan the <=3 winning groups exactly (bit-identical math)
        float t0 = BIG, t1 = BIG, t2 = BIG, f0 = 0.f, f1 = 0.f, f2 = 0.f;
        const float4* fvb = reinterpret_cast<const float4*>(fvbufs[s]);
#pragma unroll
        for (int j = 0; j < 3; j++) {
            int gg = (j == 0) ? g0 : (j == 1) ? g1 : g2;
            float mm = (j == 0) ? m0 : (j == 1) ? m1 : m2;
            if (gg >= 0 && mm < SENT) {
                float d0, d1, d2, d3;
                group_d(buf, gg, c2x, c2y, c2z, qq2, d0, d1, d2, d3);
                float4 F = __ldg(fvb + gg);
                try_ins(d0, F.x, t0, t1, t2, f0, f1, f2);
                try_ins(d1, F.y, t0, t1, t2, f0, f1, f2);
                try_ins(d2, F.z, t0, t1, t2, f0, f1, f2);
                try_ins(d3, F.w, t0, t1, t2, f0, f1, f2);
            }
        }

        // butterfly merge across the 4 team lanes
#pragma unroll
        for (int o = 1; o <= 2; o <<= 1) {
            float rt0 = __shfl_xor_sync(FULL, t0, o), rf0 = __shfl_xor_sync(FULL, f0, o);
            float rt1 = __shfl_xor_sync(FULL, t1, o), rf1 = __shfl_xor_sync(FULL, f1, o);
            float rt2 = __shfl_xor_sync(FULL, t2, o), rf2 = __shfl_xor_sync(FULL, f2, o);
            try_ins(rt0, rf0, t0, t1, t2, f0, f1, f2);
            try_ins(rt1, rf1, t0, t1, t2, f0, f1, f2);
            try_ins(rt2, rf2, t0, t1, t2, f0, f1, f2);
        }
        float d0 = fmaxf(t0, 0.f), d1 = fmaxf(t1, 0.f), d2c = fmaxf(t2, 0.f);
        float r0 = 1.f / (d0 + 1e-8f);
        float r1 = 1.f / (d1 + 1e-8f);
        float r2 = 1.f / (d2c + 1e-8f);
        pred += fmaf(r0, f0, fmaf(r1, f1, r2 * f2)) / (r0 + r1 + r2);
    }

    // ---- mask: any(d2 < 0.25) over bins [cmin-1, cmax+1] (1m bins cover 0.5m) ----
    int found = 0;
    {
        const int* offs = goffs + (12 + b) * (NB + 1);
        const int gb0 = b * CAPGM;
        int bl = max(cmin - 1, 0), bh = min(cmax + 1, NB - 1);
        int gs = gb0 + (__ldg(offs + bl) >> 2);
        int ge = gb0 + (__ldg(offs + bh + 1) >> 2);
        float tf = 0.3125f - qq;                 // margin fast path
#pragma unroll 2
        for (int g = gs + sub; g < ge; g += 4) {
            const char* p = reinterpret_cast<const char*>(gmbuf) + (size_t)g * 64;
            ulonglong2 X = __ldg(reinterpret_cast<const ulonglong2*>(p));
            ulonglong2 Y = __ldg(reinterpret_cast<const ulonglong2*>(p + 16));
            ulonglong2 Z = __ldg(reinterpret_cast<const ulonglong2*>(p + 32));
            ulonglong2 W = __ldg(reinterpret_cast<const ulonglong2*>(p + 48));
            // fast path: e = kk - 2*dot (qq deferred; protected by margin)
            u64 el = ffma2u(c2x, X.x, ffma2u(c2y, Y.x, ffma2u(c2z, Z.x, W.x)));
            u64 eh = ffma2u(c2x, X.y, ffma2u(c2y, Y.y, ffma2u(c2z, Z.y, W.y)));
            float m = fminf(fminf(lo_(el), hi_(el)), fminf(lo_(eh), hi_(eh)));
            if (m < tf) {                        // rare: exact recheck
                float cx[4] = { lo_(X.x), hi_(X.x), lo_(X.y), hi_(X.y) };
                float cy[4] = { lo_(Y.x), hi_(Y.x), lo_(Y.y), hi_(Y.y) };
                float cz[4] = { lo_(Z.x), hi_(Z.x), lo_(Z.y), hi_(Z.y) };
                float cw[4] = { lo_(W.x), hi_(W.x), lo_(W.y), hi_(W.y) };
#pragma unroll
                for (int c = 0; c < 4; c++) {
                    // bit-exact reference-mimic rounding
                    float dot = __fadd_rn(__fadd_rn(__fmul_rn(x, cx[c]),
                                                    __fmul_rn(y, cy[c])),
                                          __fmul_rn(z, cz[c]));
                    float d = __fsub_rn(__fadd_rn(qq, cw[c]), __fadd_rn(dot, dot));
                    if (d < 0.25f) found = 1;
                }
            }
        }
        found |= __shfl_xor_sync(FULL, found, 1);
        found |= __shfl_xor_sync(FULL, found, 2);
    }

    if (sub == 0) {
        out[oi] = pred;                          // pred_hm (B,N,1)
        out[Bn * Nn + oi] = found ? 1.f : 0.f;   // gt_hm   (B,N)
    }
}

// ---------------- launch ---------------------------------------------------------------
extern "C" void kernel_launch(void* const* d_in, const int* in_sizes, int n_in,
                              void* d_out, int out_size) {
    (void)in_sizes; (void)n_in; (void)out_size;
    const float* pts    = (const float*)d_in[0];
    const float* known2 = (const float*)d_in[1];
    const float* feats2 = (const float*)d_in[2];
    const float* known3 = (const float*)d_in[3];
    const float* feats3 = (const float*)d_in[4];
    const float* known4 = (const float*)d_in[5];
    const float* feats4 = (const float*)d_in[6];
    const float* matchp = (const float*)d_in[7];
    const float* w_fc   = (const float*)d_in[8];
    const float* w_cls  = (const float*)d_in[9];
    float* out = (float*)d_out;

    constexpr int INIT_N = Bn * (CAPG2 + CAPG3 + CAPG4 + CAPGM) + 20 * NB;
    const int eb = (TOTAL_ELEMS + 255) / 256;
    init_kernel<<<(INIT_N + 255) / 256, 256>>>();
    hist_kernel<<<eb, 256>>>(known2, known3, known4, matchp, pts, w_fc, w_cls);
    prefix_kernel<<<1, 640>>>();
    scatter_kernel<<<eb, 256>>>(known2, feats2, known3, feats3,
                                known4, feats4, matchp, pts);
    scan_kernel<<<(Bn * Nn) / 64, 256>>>(out);   // 4 lanes/query, 4096 warps
}

// round 13
// speedup vs baseline: 2.6569x; 1.5650x over previous
#include <cuda_runtime.h>

using u64 = unsigned long long;

// ---------------- problem constants (fixed shapes) -------------------------
constexpr int Bn = 4;
constexpr int Nn = 8192;
constexpr int Cc = 32;
constexpr int M2 = 8192;
constexpr int M3 = 4096;
constexpr int M4 = 2048;
constexpr int MM = 4096;

constexpr int Q     = 2;           // queries per lane
constexpr int QPB   = 64;          // queries per block (32 lanes * Q)
constexpr int PARTS = 8;           // warps per block (candidate partitions)
constexpr int NT    = 256;
constexpr float BIG = 3.0e38f;

// ---------------- device scratch --------------------------------------------
// geometry records per 4-cand group: [x4|y4|z4|kk4] = 64 B
__device__ __align__(16) float g2buf[Bn * M2 * 4];
__device__ __align__(16) float g3buf[Bn * M3 * 4];
__device__ __align__(16) float g4buf[Bn * M4 * 4];
__device__ __align__(16) float gmbuf[Bn * MM * 4];
// fv payloads: flat per-element; group g owns [4g..4g+3] (float4-loadable)
__device__ __align__(16) float fv2buf[Bn * M2];
__device__ __align__(16) float fv3buf[Bn * M3];
__device__ __align__(16) float fv4buf[Bn * M4];

// ---------------- packed f32x2 helpers --------------------------------------
__device__ __forceinline__ u64 ffma2u(u64 a, u64 b, u64 c) {
    u64 r;
    asm("fma.rn.f32x2 %0, %1, %2, %3;" : "=l"(r) : "l"(a), "l"(b), "l"(c));
    return r;
}
__device__ __forceinline__ u64 fadd2u(u64 a, u64 b) {
    u64 r;
    asm("add.rn.f32x2 %0, %1, %2;" : "=l"(r) : "l"(a), "l"(b));
    return r;
}
__device__ __forceinline__ float lo_(u64 v) { return __uint_as_float((unsigned)v); }
__device__ __forceinline__ float hi_(u64 v) { return __uint_as_float((unsigned)(v >> 32)); }
__device__ __forceinline__ u64 dup2(float x) {
    unsigned b = __float_as_uint(x);
    return ((u64)b << 32) | (u64)b;
}

// ---------------- precompute: pack records + fv ------------------------------
__global__ void precompute_kernel(
    const float* __restrict__ known2, const float* __restrict__ feats2,
    const float* __restrict__ known3, const float* __restrict__ feats3,
    const float* __restrict__ known4, const float* __restrict__ feats4,
    const float* __restrict__ matchp,
    const float* __restrict__ w_fc, const float* __restrict__ w_cls)
{
    __shared__ float sv[96];                    // v = w_cls @ w_fc (per-block)
    int t = threadIdx.x;
    if (t < 96) {
        float acc = 0.f;
#pragma unroll
        for (int k = 0; k < 64; k++) acc = fmaf(w_cls[k], w_fc[k * 96 + t], acc);
        sv[t] = acc;
    }
    __syncthreads();

    int idx = blockIdx.x * NT + t;
    constexpr int A = Bn * M2;
    constexpr int B = A + Bn * M3;
    constexpr int C = B + Bn * M4;
    constexpr int D = C + Bn * MM;

    const float* known; const float* feats; float* buf; float* fvb; int i, voff;
    if (idx < A)      { known = known2; feats = feats2; buf = g2buf; fvb = fv2buf; i = idx;     voff = 0;  }
    else if (idx < B) { known = known3; feats = feats3; buf = g3buf; fvb = fv3buf; i = idx - A; voff = 32; }
    else if (idx < C) { known = known4; feats = feats4; buf = g4buf; fvb = fv4buf; i = idx - B; voff = 64; }
    else if (idx < D) {
        int i2 = idx - C;
        float x = matchp[3 * i2 + 0];
        float y = matchp[3 * i2 + 1];
        float z = matchp[3 * i2 + 2];
        float kk = __fadd_rn(__fadd_rn(__fmul_rn(x, x), __fmul_rn(y, y)), __fmul_rn(z, z));
        int base = (i2 >> 2) * 16 + (i2 & 3);
        gmbuf[base + 0] = x; gmbuf[base + 4] = y;
        gmbuf[base + 8] = z; gmbuf[base + 12] = kk;
        return;
    } else return;

    float x = known[3 * i + 0];
    float y = known[3 * i + 1];
    float z = known[3 * i + 2];
    // same rounding order as jnp.sum(known*known, -1)
    float kk = __fadd_rn(__fadd_rn(__fmul_rn(x, x), __fmul_rn(y, y)), __fmul_rn(z, z));

    float acc = 0.f;
    const float4* f4 = reinterpret_cast<const float4*>(feats + (size_t)i * Cc);
#pragma unroll
    for (int j = 0; j < 8; j++) {
        float4 tt = f4[j];
        acc = fmaf(tt.x, sv[voff + 4 * j + 0], acc);
        acc = fmaf(tt.y, sv[voff + 4 * j + 1], acc);
        acc = fmaf(tt.z, sv[voff + 4 * j + 2], acc);
        acc = fmaf(tt.w, sv[voff + 4 * j + 3], acc);
    }
    int base = (i >> 2) * 16 + (i & 3);
    buf[base + 0]  = x;  buf[base + 4]  = y;
    buf[base + 8]  = z;  buf[base + 12] = kk;
    fvb[i] = acc;
}

// ---------------- top-3 maintenance ------------------------------------------
__device__ __forceinline__ void try_ins(float e, float fv, float t[3], float f[3]) {
    if (e < t[2]) {
        if (e < t[1]) {
            t[2] = t[1]; f[2] = f[1];
            if (e < t[0]) { t[1] = t[0]; f[1] = f[0]; t[0] = e; f[0] = fv; }
            else          { t[1] = e;    f[1] = fv; }
        } else { t[2] = e; f[2] = fv; }
    }
}
__device__ __forceinline__ void try_ins_g(float e, int g, float m[3], int gi[3]) {
    if (e < m[1]) {
        m[2] = m[1]; gi[2] = gi[1];
        if (e < m[0]) { m[1] = m[0]; gi[1] = gi[0]; m[0] = e; gi[0] = g; }
        else          { m[1] = e;    gi[1] = g; }
    } else { m[2] = e; gi[2] = g; }
}

// packed distances of one 64B group record; reference rounding order
__device__ __forceinline__ void group_d(const float* buf, int g,
    u64 c2x, u64 c2y, u64 c2z, u64 qq2,
    float& d0, float& d1, float& d2, float& d3)
{
    const char* p = reinterpret_cast<const char*>(buf) + (size_t)g * 64;
    ulonglong2 X = __ldg(reinterpret_cast<const ulonglong2*>(p));
    ulonglong2 Y = __ldg(reinterpret_cast<const ulonglong2*>(p + 16));
    ulonglong2 Z = __ldg(reinterpret_cast<const ulonglong2*>(p + 32));
    ulonglong2 W = __ldg(reinterpret_cast<const ulonglong2*>(p + 48));
    u64 dl = fadd2u(qq2, W.x);
    dl = ffma2u(c2x, X.x, dl); dl = ffma2u(c2y, Y.x, dl); dl = ffma2u(c2z, Z.x, dl);
    u64 dh = fadd2u(qq2, W.y);
    dh = ffma2u(c2x, X.y, dh); dh = ffma2u(c2y, Y.y, dh); dh = ffma2u(c2z, Z.y, dh);
    d0 = lo_(dl); d1 = hi_(dl); d2 = lo_(dh); d3 = hi_(dh);
}

// ---------------- interp scan: group-min top-3 + exact rescan -----------------
__device__ __forceinline__ void scan_set(
    const float* __restrict__ buf, const float* __restrict__ fvb,
    int grp0, int Mg,
    const u64 c2x[Q], const u64 c2y[Q], const u64 c2z[Q], const u64 qq2[Q],
    float t[Q][3], float f[Q][3])
{
    float m[Q][3]; int gi[Q][3];
#pragma unroll
    for (int j = 0; j < Q; j++) {
        m[j][0] = m[j][1] = m[j][2] = BIG;
        gi[j][0] = gi[j][1] = gi[j][2] = -1;
    }
    const char* p = reinterpret_cast<const char*>(buf) + (size_t)grp0 * 64;
#pragma unroll 2
    for (int g = grp0; g < grp0 + Mg; g++, p += 64) {
        ulonglong2 X = __ldg(reinterpret_cast<const ulonglong2*>(p));
        ulonglong2 Y = __ldg(reinterpret_cast<const ulonglong2*>(p + 16));
        ulonglong2 Z = __ldg(reinterpret_cast<const ulonglong2*>(p + 32));
        ulonglong2 W = __ldg(reinterpret_cast<const ulonglong2*>(p + 48));
#pragma unroll
        for (int j = 0; j < Q; j++) {
            u64 dl = fadd2u(qq2[j], W.x);
            dl = ffma2u(c2x[j], X.x, dl);
            dl = ffma2u(c2y[j], Y.x, dl);
            dl = ffma2u(c2z[j], Z.x, dl);
            u64 dh = fadd2u(qq2[j], W.y);
            dh = ffma2u(c2x[j], X.y, dh);
            dh = ffma2u(c2y[j], Y.y, dh);
            dh = ffma2u(c2z[j], Z.y, dh);
            float mm = fminf(fminf(lo_(dl), hi_(dl)), fminf(lo_(dh), hi_(dh)));
            if (mm < m[j][2]) try_ins_g(mm, g, m[j], gi[j]);   // single insert
        }
    }

    // exact rescan of the <=3 winning groups per query (bit-identical math)
    const float4* fv4 = reinterpret_cast<const float4*>(fvb);
#pragma unroll
    for (int j = 0; j < Q; j++) {
        t[j][0] = t[j][1] = t[j][2] = BIG;
        f[j][0] = f[j][1] = f[j][2] = 0.f;
#pragma unroll
        for (int k = 0; k < 3; k++) {
            int gg = gi[j][k];
            if (gg >= 0) {
                float d0, d1, d2, d3;
                group_d(buf, gg, c2x[j], c2y[j], c2z[j], qq2[j], d0, d1, d2, d3);
                float4 F = __ldg(fv4 + gg);
                try_ins(d0, F.x, t[j], f[j]);
                try_ins(d1, F.y, t[j], f[j]);
                try_ins(d2, F.z, t[j], f[j]);
                try_ins(d3, F.w, t[j], f[j]);
            }
        }
    }
}

// ---------------- mask scan: any(d2 < 0.25), margin + exact recheck -----------
__device__ __forceinline__ void scan_mask(
    const float* __restrict__ buf, int grp0, int Mg,
    const u64 c2x[Q], const u64 c2y[Q], const u64 c2z[Q], const u64 qq2[Q],
    bool found[Q])
{
    float tf[Q], qx[Q], qy[Q], qz[Q], qqv[Q];
#pragma unroll
    for (int j = 0; j < Q; j++) {
        found[j] = false;
        qqv[j] = lo_(qq2[j]);
        tf[j]  = 0.3125f - qqv[j];               // e < 0.25 + 0.0625 margin
        qx[j]  = -0.5f * lo_(c2x[j]);            // exact (pow2 scale)
        qy[j]  = -0.5f * lo_(c2y[j]);
        qz[j]  = -0.5f * lo_(c2z[j]);
    }
    const char* p = reinterpret_cast<const char*>(buf) + (size_t)grp0 * 64;
#pragma unroll 2
    for (int g = 0; g < Mg; g++, p += 64) {
        ulonglong2 X = __ldg(reinterpret_cast<const ulonglong2*>(p));
        ulonglong2 Y = __ldg(reinterpret_cast<const ulonglong2*>(p + 16));
        ulonglong2 Z = __ldg(reinterpret_cast<const ulonglong2*>(p + 32));
        ulonglong2 W = __ldg(reinterpret_cast<const ulonglong2*>(p + 48));
#pragma unroll
        for (int j = 0; j < Q; j++) {
            // fast path: e = kk - 2*dot (qq deferred; protected by margin)
            u64 el = ffma2u(c2x[j], X.x, ffma2u(c2y[j], Y.x, ffma2u(c2z[j], Z.x, W.x)));
            u64 eh = ffma2u(c2x[j], X.y, ffma2u(c2y[j], Y.y, ffma2u(c2z[j], Z.y, W.y)));
            float mm = fminf(fminf(lo_(el), hi_(el)), fminf(lo_(eh), hi_(eh)));
            if (mm < tf[j]) {                     // rare: exact recheck
                float cx[4] = { lo_(X.x), hi_(X.x), lo_(X.y), hi_(X.y) };
                float cy[4] = { lo_(Y.x), hi_(Y.x), lo_(Y.y), hi_(Y.y) };
                float cz[4] = { lo_(Z.x), hi_(Z.x), lo_(Z.y), hi_(Z.y) };
                float cw[4] = { lo_(W.x), hi_(W.x), lo_(W.y), hi_(W.y) };
#pragma unroll
                for (int c = 0; c < 4; c++) {
                    // bit-exact reference-mimic rounding
                    float dot = __fadd_rn(__fadd_rn(__fmul_rn(qx[j], cx[c]),
                                                    __fmul_rn(qy[j], cy[c])),
                                          __fmul_rn(qz[j], cz[c]));
                    float d = __fsub_rn(__fadd_rn(qqv[j], cw[c]),
                                        __fadd_rn(dot, dot));
                    if (d < 0.25f) found[j] = true;
                }
            }
        }
    }
}

// ---------------- merge 24 partial top-3 entries -------------------------------
__device__ __forceinline__ float merge_one(const float2* __restrict__ ent) {
    float t[3] = {BIG, BIG, BIG}, f[3] = {0.f, 0.f, 0.f};
#pragma unroll
    for (int k = 0; k < PARTS * 3; k++) {
        float2 c = ent[k];
        try_ins(c.x, c.y, t, f);
    }
    float d0 = fmaxf(t[0], 0.f);
    float d1 = fmaxf(t[1], 0.f);
    float d2 = fmaxf(t[2], 0.f);
    float r0 = 1.f / (d0 + 1e-8f);
    float r1 = 1.f / (d1 + 1e-8f);
    float r2 = 1.f / (d2 + 1e-8f);
    return fmaf(r0, f[0], fmaf(r1, f[1], r2 * f[2])) / (r0 + r1 + r2);
}

// ---------------- fused main kernel ---------------------------------------------
// grid = 512 blocks; with <=64 regs all 512 co-resident (4 per SM): one wave
__global__ void __launch_bounds__(NT, 4)
fused_kernel(const float* __restrict__ pts, float* __restrict__ out) {
    __shared__ float2 s_m[QPB * PARTS * 3];      // 12 KB merge scratch

    const int tid  = threadIdx.x;
    const int qslot = tid & 31;                  // lane
    const int part = tid >> 5;                   // warp id == candidate part
    const int b    = (blockIdx.x * QPB) >> 13;   // batch

    u64 c2x[Q], c2y[Q], c2z[Q], qq2[Q];
#pragma unroll
    for (int j = 0; j < Q; j++) {
        int gq = blockIdx.x * QPB + 2 * qslot + j;
        float x = pts[3 * gq + 0];
        float y = pts[3 * gq + 1];
        float z = pts[3 * gq + 2];
        float qq = __fadd_rn(__fadd_rn(__fmul_rn(x, x), __fmul_rn(y, y)),
                             __fmul_rn(z, z));
        c2x[j] = dup2(-2.f * x);
        c2y[j] = dup2(-2.f * y);
        c2z[j] = dup2(-2.f * z);
        qq2[j] = dup2(qq);
    }

    float pred = 0.f;                            // meaningful for tid < QPB
    float t[Q][3], f[Q][3];

    const float* sb[3]  = { g2buf, g3buf, g4buf };
    const float* sfv[3] = { fv2buf, fv3buf, fv4buf };
    const int    sM[3]  = { M2, M3, M4 };

#pragma unroll 1
    for (int s = 0; s < 3; s++) {
        const int Mg = sM[s] / (4 * PARTS);      // groups per part
        const int grp0 = (b * sM[s]) / 4 + part * Mg;
        scan_set(sb[s], sfv[s], grp0, Mg, c2x, c2y, c2z, qq2, t, f);
#pragma unroll
        for (int j = 0; j < Q; j++) {
            int q = 2 * qslot + j;
            int bse = (q * PARTS + part) * 3;
            s_m[bse + 0] = make_float2(t[j][0], f[j][0]);
            s_m[bse + 1] = make_float2(t[j][1], f[j][1]);
            s_m[bse + 2] = make_float2(t[j][2], f[j][2]);
        }
        __syncthreads();
        if (tid < QPB) pred += merge_one(s_m + tid * PARTS * 3);
        __syncthreads();
    }

    bool found[Q];
    {
        const int Mg = MM / (4 * PARTS);
        const int grp0 = (b * MM) / 4 + part * Mg;
        scan_mask(gmbuf + (size_t)grp0 * 0 + 0, grp0, Mg, c2x, c2y, c2z, qq2, found);
    }

    float* s_fl = reinterpret_cast<float*>(s_m);
#pragma unroll
    for (int j = 0; j < Q; j++)
        s_fl[(2 * qslot + j) * PARTS + part] = found[j] ? 1.f : 0.f;
    __syncthreads();
    if (tid < QPB) {
        float fl = 0.f;
#pragma unroll
        for (int k = 0; k < PARTS; k++) fl = fmaxf(fl, s_fl[tid * PARTS + k]);
        int gq = blockIdx.x * QPB + tid;
        out[gq] = pred;                          // pred_hm (B,N,1)
        out[Bn * Nn + gq] = fl;                  // gt_hm   (B,N)
    }
}

// ---------------- launch ----------------------------------------------------------
extern "C" void kernel_launch(void* const* d_in, const int* in_sizes, int n_in,
                              void* d_out, int out_size) {
    (void)in_sizes; (void)n_in; (void)out_size;
    const float* pts    = (const float*)d_in[0];
    const float* known2 = (const float*)d_in[1];
    const float* feats2 = (const float*)d_in[2];
    const float* known3 = (const float*)d_in[3];
    const float* feats3 = (const float*)d_in[4];
    const float* known4 = (const float*)d_in[5];
    const float* feats4 = (const float*)d_in[6];
    const float* matchp = (const float*)d_in[7];
    const float* w_fc   = (const float*)d_in[8];
    const float* w_cls  = (const float*)d_in[9];
    float* out = (float*)d_out;

    constexpr int total = Bn * (M2 + M3 + M4 + MM);
    precompute_kernel<<<(total + NT - 1) / NT, NT>>>(
        known2, feats2, known3, feats3, known4, feats4, matchp, w_fc, w_cls);
    fused_kernel<<<(Bn * Nn) / QPB, NT>>>(pts, out);
}